// round 9
// baseline (speedup 1.0000x reference)
#include <cuda_runtime.h>
#include <cstdint>
#include <math.h>

#define BATCH 8
#define CIN   28
#define COUT  28
#define HH    256
#define WW    256
#define DGRP  7
#define KHT   7
#define CPG   4
#define HW    (HH*WW)

typedef unsigned long long ull;

__device__ __forceinline__ ull pk2(float a, float b) {
    ull r; asm("mov.b64 %0, {%1,%2};" : "=l"(r) : "f"(a), "f"(b)); return r;
}
__device__ __forceinline__ ull pk1(float a) { return pk2(a, a); }
__device__ __forceinline__ ull f2fma(ull a, ull b, ull c) {
    ull d; asm("fma.rn.f32x2 %0, %1, %2, %3;" : "=l"(d) : "l"(a), "l"(b), "l"(c)); return d;
}
__device__ __forceinline__ ull f2mul(ull a, ull b) {
    ull d; asm("mul.rn.f32x2 %0, %1, %2;" : "=l"(d) : "l"(a), "l"(b)); return d;
}
__device__ __forceinline__ ull splat_dev(float v) {
    unsigned u = __float_as_uint(v); return ((ull)u << 32) | (ull)u;
}

// ---- precomputed weights ----
__device__ ull   g_W1P[2 * DGRP * KHT * CPG * 2 * 7];   // [tap][c][ohh][j] -> ull2 splat pair
__device__ float g_W2F[COUT * 7 * 4 * 8];               // [o2][kw][ohq][8] floats (7 used)
__device__ float g_b2[COUT];

__global__ void prep_kernel(const float* __restrict__ weight, const float* __restrict__ w_t,
                            const float* __restrict__ b_t, const float* __restrict__ w_m,
                            const float* __restrict__ b_m) {
    int gid = blockIdx.x * blockDim.x + threadIdx.x;
    int nth = gridDim.x * blockDim.x;

    // W1P: e = ((tap*4+c)*2+ohh)*7+j ; channels 2j, 2j+1 of half ohh (splat pairs)
    for (int e = gid; e < 2744; e += nth) {
        int j = e % 7; int r = e / 7;
        int ohh = r & 1; r >>= 1;
        int c = r & 3; int tap = r >> 2;
        int g = tap / 7, i = tap % 7;
        int o0 = ohh * 14 + 2 * j;
        float wa = weight[(o0 * CIN + (g * CPG + c)) * KHT + i];
        float wb = weight[((o0 + 1) * CIN + (g * CPG + c)) * KHT + i];
        g_W1P[2 * e]     = splat_dev(wa);
        g_W1P[2 * e + 1] = splat_dev(wb);
    }

    // W2F (stage-3 folded): offset = ((o2*7+kw)*4+ohq)*8 + j ; channel = ohq*7+j
    for (int e = gid; e < 6272; e += nth) {
        int j = e & 7; int q = e >> 3;
        int ohq = q & 3; q >>= 2;
        int kw = q % 7; int o2 = q / 7;
        float v = 0.f;
        if (j < 7) {
            int oc = ohq * 7 + j;
            int f = oc >> 2, cc = oc & 3;
#pragma unroll
            for (int g = 0; g < DGRP; g++)
                v += w_m[f * DGRP + g] * w_t[((g * CPG + cc) * COUT + o2) * 7 + kw];
        }
        g_W2F[e] = v;
    }

    if (gid < COUT) {
        int f = gid >> 2, cc = gid & 3;
        float s = 0.f;
#pragma unroll
        for (int g = 0; g < DGRP; g++) s += w_m[f * DGRP + g] * b_t[g * CPG + cc];
        g_b2[gid] = s + b_m[f];
    }
}

// ---- fused kernel smem layout (bytes) ----
constexpr int F_W1   = 0;                        // ull[5488]  43904
constexpr int F_W2   = 43904;                    // float[6272] 25088
constexpr int F_B1   = 68992;                    // float[32]
constexpr int F_B2   = 69120;                    // float[32]
constexpr int F_TL0  = 69248;                    // ull[64]
constexpr int F_TL1  = 69760;                    // ull[64]
constexpr int F_TY0  = 70272;                    // int[64]  (premult by WW)
constexpr int F_TY1  = 70528;                    // int[64]
constexpr int F_R    = 70784;                    // float[28*264] 29568
constexpr int F_SMEM = F_R + 29568;              // 100352 (~98KB) -> 2 CTAs/SM

__global__ void __launch_bounds__(256, 2)
fused_kernel(const float* __restrict__ x, const float* __restrict__ bias1,
             float* __restrict__ out) {
    extern __shared__ char sm[];
    ull*   W1p = (ull*)(sm + F_W1);
    float* W2f = (float*)(sm + F_W2);
    float* b1s = (float*)(sm + F_B1);
    float* b2s = (float*)(sm + F_B2);
    ull*   tl0 = (ull*)(sm + F_TL0);
    ull*   tl1 = (ull*)(sm + F_TL1);
    int*   ty0 = (int*)(sm + F_TY0);
    int*   ty1 = (int*)(sm + F_TY1);
    float* R   = (float*)(sm + F_R);

    const int tid = threadIdx.x;
    const int h = blockIdx.x;
    const int b = blockIdx.y;

    for (int i = tid; i < 5488; i += 256) W1p[i] = g_W1P[i];
    for (int i = tid; i < 6272; i += 256) W2f[i] = g_W2F[i];
    if (tid < 28) { b1s[tid] = bias1[tid]; b2s[tid] = g_b2[tid]; }

    if (tid < 49) {
        int g = tid / 7, i = tid % 7;
        double yp = (double)((h + 1) * (i + 1)) / (double)(g + 1) - 4.0;
        double y0 = floor(yp);
        float fy = (float)(yp - y0);
        int y0i = (int)y0;
        bool v0 = (y0i >= 0) && (y0i <= HH - 1);
        bool v1 = (y0i + 1 >= 0) && (y0i + 1 <= HH - 1);
        int ya = y0i < 0 ? 0 : (y0i > HH - 1 ? HH - 1 : y0i);
        int yb = (y0i + 1) < 0 ? 0 : (y0i + 1 > HH - 1 ? HH - 1 : y0i + 1);
        ty0[tid] = ya * WW;
        ty1[tid] = yb * WW;
        tl0[tid] = v0 ? pk1(1.0f - fy) : 0ull;
        tl1[tid] = v1 ? pk1(fy) : 0ull;
    }

    // R halos
    if (tid < 28) {
        float* Rr = R + tid * 264;
        Rr[0] = Rr[1] = Rr[2] = Rr[3] = 0.f;
        Rr[260] = Rr[261] = Rr[262] = Rr[263] = 0.f;
    }
    __syncthreads();

    // ================= Phase A: harmonic sample + 1st contraction =================
    {
        const int p = tid & 127;
        const int ohh = tid >> 7;
        const int wb = 2 * p;

        ull acc[14];
#pragma unroll
        for (int o = 0; o < 14; o++) acc[o] = pk1(b1s[ohh * 14 + o]);

        const float* rbg = x + (size_t)b * CIN * HW + wb;

#pragma unroll 1
        for (int g = 0; g < 7; g++, rbg += (size_t)CPG * HW) {
#pragma unroll 1
            for (int i = 0; i < 7; i++) {
                const int tap = g * 7 + i;
                const ull lw0 = tl0[tap], lw1 = tl1[tap];
                if ((lw0 | lw1) == 0ull) continue;   // uniform across CTA
                const int y0 = ty0[tap], y1 = ty1[tap];
                ull s[4];
#pragma unroll
                for (int c = 0; c < 4; c++) {
                    ull xv0 = *(const ull*)(rbg + (size_t)c * HW + y0);
                    ull xv1 = *(const ull*)(rbg + (size_t)c * HW + y1);
                    s[c] = f2fma(lw1, xv1, f2mul(lw0, xv0));
                }
#pragma unroll
                for (int c = 0; c < 4; c++) {
                    const ulonglong2* wc = (const ulonglong2*)W1p + ((tap * 4 + c) * 2 + ohh) * 7;
#pragma unroll
                    for (int j = 0; j < 7; j++) {
                        ulonglong2 w = wc[j];
                        acc[2 * j]     = f2fma(w.x, s[c], acc[2 * j]);
                        acc[2 * j + 1] = f2fma(w.y, s[c], acc[2 * j + 1]);
                    }
                }
            }
        }

        // write mid row into smem R (interior offset +4)
#pragma unroll
        for (int o = 0; o < 14; o++)
            *(ull*)(R + (ohh * 14 + o) * 264 + 4 + wb) = acc[o];
    }
    __syncthreads();

    // ================= Phase B: 1x7 conv along W (+ stage-3 folded) =================
    {
        const int p2 = tid & 63;
        const int ohq = tid >> 6;
        const int base = 4 * p2;

        ull a2[7][2];
#pragma unroll
        for (int o = 0; o < 7; o++) { ull bv = pk1(b2s[ohq * 7 + o]); a2[o][0] = bv; a2[o][1] = bv; }

#pragma unroll 1
        for (int o2 = 0; o2 < 28; o2++) {
            const float4* Rw = (const float4*)(R + o2 * 264 + base);
            float r[12];
            *(float4*)(r)     = Rw[0];
            *(float4*)(r + 4) = Rw[1];
            *(float4*)(r + 8) = Rw[2];
            const float* wbp = W2f + (((o2 * 7) * 4 + ohq) << 3);
#pragma unroll
            for (int kw = 0; kw < 7; kw++) {
                ull vA = pk2(r[kw + 1], r[kw + 2]);
                ull vB = pk2(r[kw + 3], r[kw + 4]);
                float4 wa = *(const float4*)(wbp + kw * 32);
                float4 wc = *(const float4*)(wbp + kw * 32 + 4);
                ull W0 = pk1(wa.x), W1 = pk1(wa.y), W2 = pk1(wa.z), W3 = pk1(wa.w);
                ull W4 = pk1(wc.x), W5 = pk1(wc.y), W6 = pk1(wc.z);
                a2[0][0] = f2fma(W0, vA, a2[0][0]); a2[0][1] = f2fma(W0, vB, a2[0][1]);
                a2[1][0] = f2fma(W1, vA, a2[1][0]); a2[1][1] = f2fma(W1, vB, a2[1][1]);
                a2[2][0] = f2fma(W2, vA, a2[2][0]); a2[2][1] = f2fma(W2, vB, a2[2][1]);
                a2[3][0] = f2fma(W3, vA, a2[3][0]); a2[3][1] = f2fma(W3, vB, a2[3][1]);
                a2[4][0] = f2fma(W4, vA, a2[4][0]); a2[4][1] = f2fma(W4, vB, a2[4][1]);
                a2[5][0] = f2fma(W5, vA, a2[5][0]); a2[5][1] = f2fma(W5, vB, a2[5][1]);
                a2[6][0] = f2fma(W6, vA, a2[6][0]); a2[6][1] = f2fma(W6, vB, a2[6][1]);
            }
        }

        float* ob = out + (((size_t)b * COUT + ohq * 7) * HH + h) * WW + base;
#pragma unroll
        for (int o = 0; o < 7; o++) {
            ulonglong2 v; v.x = a2[o][0]; v.y = a2[o][1];
            *(ulonglong2*)(ob + (size_t)o * HW) = v;
        }
    }
}

extern "C" void kernel_launch(void* const* d_in, const int* in_sizes, int n_in,
                              void* d_out, int out_size) {
    const float* x      = (const float*)d_in[0];
    const float* weight = (const float*)d_in[1];
    const float* bias   = (const float*)d_in[2];
    const float* w_t    = (const float*)d_in[3];
    const float* b_t    = (const float*)d_in[4];
    const float* w_m    = (const float*)d_in[5];
    const float* b_m    = (const float*)d_in[6];
    float* out = (float*)d_out;

    cudaFuncSetAttribute(fused_kernel, cudaFuncAttributeMaxDynamicSharedMemorySize, F_SMEM);

    prep_kernel<<<32, 256>>>(weight, w_t, b_t, w_m, b_m);
    fused_kernel<<<dim3(HH, BATCH), 256, F_SMEM>>>(x, bias, out);
}